// round 1
// baseline (speedup 1.0000x reference)
#include <cuda_runtime.h>
#include <cuda_bf16.h>

// out_q(x0,x1) = sum_{a,b in 0..4} coef[q][a][b] * c0^(4-a) s0^a * c1^(4-b) s1^b
// where c0=cos(x0/2), s0=sin(x0/2), etc.
// coef derived from A_q = Re(U^dag Z_q U) with U = fixed variational circuit.

__device__ float g_coef[100]; // [q][a][b] flattened: q*25 + a*5 + b

// ---------------------------------------------------------------------------
// Setup kernel: one block, 256 threads. Simulates the 16x16 variational
// unitary (columns = basis states), builds A_q, collapses to 100 coefficients.
// ---------------------------------------------------------------------------
__global__ void qnn_setup_kernel(const float* __restrict__ w) {
    __shared__ float2 S[16][16];       // S[col][k] = amplitude k of column col
    __shared__ float A[4][16][16];
    const int tid = threadIdx.x;

    // init: identity columns
    {
        int col = tid >> 4, k = tid & 15;
        S[col][k] = make_float2((col == k) ? 1.f : 0.f, 0.f);
    }
    __syncthreads();

    // 3 layers x (RX,RY,RZ per qubit) then CNOT ring
    for (int l = 0; l < 3; l++) {
        for (int q = 0; q < 4; q++) {
            const int pos  = 3 - q;       // wire 0 = MSB
            const int mask = 1 << pos;
            for (int g = 0; g < 3; g++) {
                float th = 0.5f * w[(l * 4 + q) * 3 + g];
                float s, c;
                __sincosf(th, &s, &c);
                __syncthreads();
                if (tid < 128) {
                    int col = tid >> 3, p = tid & 7;
                    int low = p & (mask - 1);
                    int k   = ((p - low) << 1) | low;   // insert 0 at bit pos
                    float2 a = S[col][k], b = S[col][k | mask];
                    float2 na, nb;
                    if (g == 0) {        // RX: [[c,-is],[-is,c]]
                        na = make_float2(c * a.x + s * b.y, c * a.y - s * b.x);
                        nb = make_float2(c * b.x + s * a.y, c * b.y - s * a.x);
                    } else if (g == 1) { // RY: [[c,-s],[s,c]]
                        na = make_float2(c * a.x - s * b.x, c * a.y - s * b.y);
                        nb = make_float2(s * a.x + c * b.x, s * a.y + c * b.y);
                    } else {             // RZ: diag(e^{-i th}, e^{+i th})
                        na = make_float2(c * a.x + s * a.y, c * a.y - s * a.x);
                        nb = make_float2(c * b.x - s * b.y, c * b.y + s * b.x);
                    }
                    S[col][k]        = na;
                    S[col][k | mask] = nb;
                }
            }
        }
        __syncthreads();
        if (tid < 16) { // CNOT ring, per-column
            for (int q = 0; q < 4; q++) {
                int pc = 3 - q, pt = 3 - ((q + 1) & 3);
                for (int k = 0; k < 16; k++) {
                    if (((k >> pc) & 1) && !((k >> pt) & 1)) {
                        int k2 = k | (1 << pt);
                        float2 tmp = S[tid][k];
                        S[tid][k]  = S[tid][k2];
                        S[tid][k2] = tmp;
                    }
                }
            }
        }
        __syncthreads();
    }

    // A_q[i][j] = sum_k z_q(k) * Re(conj(U[k][i]) U[k][j]); U[k][i] = S[i][k]
    {
        int i = tid >> 4, j = tid & 15;
        float s0 = 0.f, s1 = 0.f, s2 = 0.f, s3 = 0.f;
        #pragma unroll
        for (int k = 0; k < 16; k++) {
            float p = S[i][k].x * S[j][k].x + S[i][k].y * S[j][k].y;
            s0 += ((k >> 3) & 1) ? -p : p;
            s1 += ((k >> 2) & 1) ? -p : p;
            s2 += ((k >> 1) & 1) ? -p : p;
            s3 += ( k       & 1) ? -p : p;
        }
        A[0][i][j] = s0; A[1][i][j] = s1; A[2][i][j] = s2; A[3][i][j] = s3;
    }
    __syncthreads();

    // Collapse: coef[q][a][b] = sum over (i,j) with matching monomial exponents.
    // a_i = #1-bits among wires {0,2} of i, b_i = among wires {1,3}.
    if (tid < 100) {
        int q = tid / 25, r = tid % 25, a = r / 5, b = r % 5;
        float sum = 0.f;
        for (int i = 0; i < 16; i++) {
            int ai = ((i >> 3) & 1) + ((i >> 1) & 1);
            int bi = ((i >> 2) & 1) + (i & 1);
            for (int j = 0; j < 16; j++) {
                int aj = ((j >> 3) & 1) + ((j >> 1) & 1);
                int bj = ((j >> 2) & 1) + (j & 1);
                if (ai + aj == a && bi + bj == b) sum += A[q][i][j];
            }
        }
        g_coef[tid] = sum;
    }
}

// ---------------------------------------------------------------------------
// Batch kernel: 1 sample / thread. Load x (float2), 2 sincos, 25-term
// bilinear form per output, store float4.
// ---------------------------------------------------------------------------
__global__ void __launch_bounds__(256)
qnn_batch_kernel(const float2* __restrict__ x, float4* __restrict__ out, int n) {
    __shared__ float sc[100];
    const int t = threadIdx.x;
    if (t < 100) sc[t] = g_coef[t];
    __syncthreads();

    int idx = blockIdx.x * blockDim.x + t;
    if (idx >= n) return;

    float2 xv = x[idx];
    float c0, s0, c1, s1;
    __sincosf(0.5f * xv.x, &s0, &c0);
    __sincosf(0.5f * xv.y, &s1, &c1);

    float c02 = c0 * c0, s02 = s0 * s0, cs0 = c0 * s0;
    float c12 = c1 * c1, s12 = s1 * s1, cs1 = c1 * s1;
    float f0[5] = { c02 * c02, c02 * cs0, cs0 * cs0, cs0 * s02, s02 * s02 };
    float f1[5] = { c12 * c12, c12 * cs1, cs1 * cs1, cs1 * s12, s12 * s12 };

    float o[4];
    #pragma unroll
    for (int q = 0; q < 4; q++) {
        float acc = 0.f;
        #pragma unroll
        for (int a = 0; a < 5; a++) {
            const float* row = &sc[q * 25 + a * 5];
            float tsum = fmaf(row[0], f1[0],
                         fmaf(row[1], f1[1],
                         fmaf(row[2], f1[2],
                         fmaf(row[3], f1[3],
                              row[4] * f1[4]))));
            acc = fmaf(tsum, f0[a], acc);
        }
        o[q] = acc;
    }
    out[idx] = make_float4(o[0], o[1], o[2], o[3]);
}

extern "C" void kernel_launch(void* const* d_in, const int* in_sizes, int n_in,
                              void* d_out, int out_size) {
    const float* x = (const float*)d_in[0];   // (B, 2)
    const float* w = (const float*)d_in[1];   // (3, 4, 3)
    int n = in_sizes[0] / 2;                  // batch size

    qnn_setup_kernel<<<1, 256>>>(w);
    int blocks = (n + 255) / 256;
    qnn_batch_kernel<<<blocks, 256>>>((const float2*)x, (float4*)d_out, n);
}

// round 2
// speedup vs baseline: 1.0030x; 1.0030x over previous
#include <cuda_runtime.h>
#include <cuda_bf16.h>

// out_q(x0,x1) = sum_{a,b in 0..4} coef[q][a][b] * c0^(4-a) s0^a * c1^(4-b) s1^b
// coef derived from A_q = Re(U^dag Z_q U), U = fixed 16x16 variational circuit.

__device__ float g_coef[100]; // [q][a][b] flattened

// ---------------- packed f32x2 helpers ----------------
typedef unsigned long long u64;
__device__ __forceinline__ u64 pk2(float lo, float hi) {
    u64 r; asm("mov.b64 %0, {%1, %2};" : "=l"(r) : "f"(lo), "f"(hi)); return r;
}
__device__ __forceinline__ void unpk2(u64 v, float& lo, float& hi) {
    asm("mov.b64 {%0, %1}, %2;" : "=f"(lo), "=f"(hi) : "l"(v));
}
__device__ __forceinline__ u64 mul2(u64 a, u64 b) {
    u64 r; asm("mul.rn.f32x2 %0, %1, %2;" : "=l"(r) : "l"(a), "l"(b)); return r;
}
__device__ __forceinline__ u64 fma2(u64 a, u64 b, u64 c) {
    u64 r; asm("fma.rn.f32x2 %0, %1, %2, %3;" : "=l"(r) : "l"(a), "l"(b), "l"(c)); return r;
}

// ---------------------------------------------------------------------------
// Setup kernel: threads 0..15 each evolve ONE column of the 16x16 unitary in
// registers (gates act on the state index only -> columns are independent,
// no barriers needed). Then one __syncthreads and the A_q / coef collapse.
// ---------------------------------------------------------------------------
__global__ void __launch_bounds__(256) qnn_setup_kernel(const float* __restrict__ w) {
    __shared__ float2 S[16][16];   // S[col][k]
    __shared__ float A[4][16][16];
    const int tid = threadIdx.x;

    if (tid < 16) {
        // column tid, amplitudes in registers
        float2 a[16];
        #pragma unroll
        for (int k = 0; k < 16; k++) a[k] = make_float2((k == tid) ? 1.f : 0.f, 0.f);

        // precompute all 36 (sin,cos) of half-angles (independent -> pipelined)
        float cc[36], ss[36];
        #pragma unroll
        for (int g = 0; g < 36; g++) {
            __sincosf(0.5f * __ldg(&w[g]), &ss[g], &cc[g]);
        }

        #pragma unroll
        for (int l = 0; l < 3; l++) {
            #pragma unroll
            for (int q = 0; q < 4; q++) {
                const int pos  = 3 - q;
                const int mask = 1 << pos;
                #pragma unroll
                for (int g = 0; g < 3; g++) {
                    const int gi = (l * 4 + q) * 3 + g;
                    const float c = cc[gi], s = ss[gi];
                    #pragma unroll
                    for (int p = 0; p < 8; p++) {
                        const int low = p & (mask - 1);
                        const int k   = ((p - low) << 1) | low;
                        const int k2  = k | mask;
                        float2 va = a[k], vb = a[k2];
                        float2 na, nb;
                        if (g == 0) {        // RX
                            na = make_float2(c * va.x + s * vb.y, c * va.y - s * vb.x);
                            nb = make_float2(c * vb.x + s * va.y, c * vb.y - s * va.x);
                        } else if (g == 1) { // RY
                            na = make_float2(c * va.x - s * vb.x, c * va.y - s * vb.y);
                            nb = make_float2(s * va.x + c * vb.x, s * va.y + c * vb.y);
                        } else {             // RZ
                            na = make_float2(c * va.x + s * va.y, c * va.y - s * va.x);
                            nb = make_float2(c * vb.x - s * vb.y, c * vb.y + s * vb.x);
                        }
                        a[k] = na; a[k2] = nb;
                    }
                }
            }
            // CNOT ring (compile-time swaps)
            #pragma unroll
            for (int q = 0; q < 4; q++) {
                const int pc = 3 - q, pt = 3 - ((q + 1) & 3);
                #pragma unroll
                for (int k = 0; k < 16; k++) {
                    if (((k >> pc) & 1) && !((k >> pt) & 1)) {
                        const int k2 = k | (1 << pt);
                        float2 tmp = a[k]; a[k] = a[k2]; a[k2] = tmp;
                    }
                }
            }
        }
        #pragma unroll
        for (int k = 0; k < 16; k++) S[tid][k] = a[k];
    }
    __syncthreads();

    // A_q[i][j] = sum_k z_q(k) * Re(conj(U[k][i]) U[k][j]); U[k][i] = S[i][k]
    {
        const int i = tid >> 4, j = tid & 15;
        float s0 = 0.f, s1 = 0.f, s2 = 0.f, s3 = 0.f;
        #pragma unroll
        for (int k = 0; k < 16; k++) {
            float p = S[i][k].x * S[j][k].x + S[i][k].y * S[j][k].y;
            s0 += ((k >> 3) & 1) ? -p : p;
            s1 += ((k >> 2) & 1) ? -p : p;
            s2 += ((k >> 1) & 1) ? -p : p;
            s3 += ( k       & 1) ? -p : p;
        }
        A[0][i][j] = s0; A[1][i][j] = s1; A[2][i][j] = s2; A[3][i][j] = s3;
    }
    __syncthreads();

    if (tid < 100) {
        const int q = tid / 25, r = tid % 25, a = r / 5, b = r % 5;
        float sum = 0.f;
        for (int i = 0; i < 16; i++) {
            int ai = ((i >> 3) & 1) + ((i >> 1) & 1);
            int bi = ((i >> 2) & 1) + (i & 1);
            for (int j = 0; j < 16; j++) {
                int aj = ((j >> 3) & 1) + ((j >> 1) & 1);
                int bj = ((j >> 2) & 1) + (j & 1);
                if (ai + aj == a && bi + bj == b) sum += A[q][i][j];
            }
        }
        g_coef[tid] = sum;
    }
}

// ---------------------------------------------------------------------------
// Batch kernel: 2 samples / thread, packed f32x2 math (lane0 = sample A,
// lane1 = sample B). float4 load of x-pairs, 2x float4 stores.
// ---------------------------------------------------------------------------
__global__ void __launch_bounds__(256)
qnn_batch_kernel(const float4* __restrict__ x, float4* __restrict__ out, int npair) {
    __shared__ u64 scp[100];   // coefficient broadcast-packed into both lanes
    const int t = threadIdx.x;
    if (t < 100) { float v = g_coef[t]; scp[t] = pk2(v, v); }
    __syncthreads();

    const int idx = blockIdx.x * blockDim.x + t;
    if (idx >= npair) return;

    const float4 xv = x[idx];   // (x0_A, x1_A, x0_B, x1_B)
    float c0a, s0a, c1a, s1a, c0b, s0b, c1b, s1b;
    __sincosf(0.5f * xv.x, &s0a, &c0a);
    __sincosf(0.5f * xv.y, &s1a, &c1a);
    __sincosf(0.5f * xv.z, &s0b, &c0b);
    __sincosf(0.5f * xv.w, &s1b, &c1b);

    const u64 c0 = pk2(c0a, c0b), s0 = pk2(s0a, s0b);
    const u64 c1 = pk2(c1a, c1b), s1 = pk2(s1a, s1b);

    const u64 c02 = mul2(c0, c0), s02 = mul2(s0, s0), cs0 = mul2(c0, s0);
    const u64 c12 = mul2(c1, c1), s12 = mul2(s1, s1), cs1 = mul2(c1, s1);
    u64 f0[5], f1[5];
    f0[0] = mul2(c02, c02); f0[1] = mul2(c02, cs0); f0[2] = mul2(cs0, cs0);
    f0[3] = mul2(cs0, s02); f0[4] = mul2(s02, s02);
    f1[0] = mul2(c12, c12); f1[1] = mul2(c12, cs1); f1[2] = mul2(cs1, cs1);
    f1[3] = mul2(cs1, s12); f1[4] = mul2(s12, s12);

    float oa[4], ob[4];
    #pragma unroll
    for (int q = 0; q < 4; q++) {
        u64 acc = 0ull;   // +0.0f in both lanes
        #pragma unroll
        for (int a = 0; a < 5; a++) {
            const u64* row = &scp[q * 25 + a * 5];
            u64 ts = mul2(row[4], f1[4]);
            ts = fma2(row[3], f1[3], ts);
            ts = fma2(row[2], f1[2], ts);
            ts = fma2(row[1], f1[1], ts);
            ts = fma2(row[0], f1[0], ts);
            acc = fma2(ts, f0[a], acc);
        }
        unpk2(acc, oa[q], ob[q]);
    }
    out[2 * idx]     = make_float4(oa[0], oa[1], oa[2], oa[3]);
    out[2 * idx + 1] = make_float4(ob[0], ob[1], ob[2], ob[3]);
}

extern "C" void kernel_launch(void* const* d_in, const int* in_sizes, int n_in,
                              void* d_out, int out_size) {
    const float* x = (const float*)d_in[0];   // (B, 2)
    const float* w = (const float*)d_in[1];   // (3, 4, 3)
    const int n     = in_sizes[0] / 2;        // batch size (even)
    const int npair = n / 2;

    qnn_setup_kernel<<<1, 256>>>(w);
    const int blocks = (npair + 255) / 256;
    qnn_batch_kernel<<<blocks, 256>>>((const float4*)x, (float4*)d_out, npair);
}